// round 3
// baseline (speedup 1.0000x reference)
#include <cuda_runtime.h>

// out[b, idx] = prod_w ( bit_{19-w}(idx) ? sin(h[b,w]) : cos(h[b,w]) ),
// h = (x + params) * 0.5. Wire w maps to idx bit (19-w).
// Single-wave layout: 1024 CTAs (16 x 64 batches), each CTA owns 64 contiguous
// hi-values of one batch -> writes one contiguous 256 KB region with
// streaming float4 stores. t_lo (low 10 idx bits product) built once per CTA.

#define N_WIRES 20
#define BATCH 64
#define HI_PER_BLOCK 64
#define THREADS 256

__global__ __launch_bounds__(THREADS, 8)
void qansatz_kernel(const float* __restrict__ x,
                    const float* __restrict__ params,
                    float* __restrict__ out)
{
    __shared__ float sc[N_WIRES];
    __shared__ float ss[N_WIRES];
    __shared__ float t_lo[1024];
    __shared__ float p_hi[HI_PER_BLOCK];

    const int b       = blockIdx.y;                    // batch
    const int hi_base = blockIdx.x * HI_PER_BLOCK;     // 16 blocks x 64 hi
    const int tid     = threadIdx.x;

    // 1) cos/sin for this batch's 20 wires
    if (tid < N_WIRES) {
        float h = (x[b * N_WIRES + tid] + params[tid]) * 0.5f;
        float c, s;
        sincosf(h, &s, &c);
        sc[tid] = c;
        ss[tid] = s;
    }
    __syncthreads();

    // 2) low-bits table: t_lo[lo] = prod_{q=0}^{9} (lo>>q & 1 ? ss[19-q] : sc[19-q])
    #pragma unroll
    for (int r = 0; r < 4; r++) {
        int lo = tid + r * 256;
        float p = 1.0f;
        #pragma unroll
        for (int q = 0; q < 10; q++)
            p *= ((lo >> q) & 1) ? ss[19 - q] : sc[19 - q];
        t_lo[lo] = p;
    }

    // 3) hi products: p_hi[i] = prod_{q=0}^{9} (h>>q & 1 ? ss[9-q] : sc[9-q])
    if (tid < HI_PER_BLOCK) {
        int h = hi_base + tid;
        float p = 1.0f;
        #pragma unroll
        for (int q = 0; q < 10; q++)
            p *= ((h >> q) & 1) ? ss[9 - q] : sc[9 - q];
        p_hi[tid] = p;
    }
    __syncthreads();

    // 4) stream out: 64 hi-values x 1024 floats, float4 per thread per iter
    size_t base = ((size_t)b << 20) + ((size_t)hi_base << 10);
    const float4* t4 = reinterpret_cast<const float4*>(t_lo);
    float4 lo4 = t4[tid];
    float4* dst0 = reinterpret_cast<float4*>(out + base) + tid;

    #pragma unroll 8
    for (int i = 0; i < HI_PER_BLOCK; i++) {
        float ph = p_hi[i];
        float4 v;
        v.x = ph * lo4.x;
        v.y = ph * lo4.y;
        v.z = ph * lo4.z;
        v.w = ph * lo4.w;
        __stcs(dst0 + i * 256, v);   // streaming store: write-once output
    }
}

extern "C" void kernel_launch(void* const* d_in, const int* in_sizes, int n_in,
                              void* d_out, int out_size)
{
    const float* x      = (const float*)d_in[0];   // (64, 20)
    const float* params = (const float*)d_in[1];   // (20,)
    float* out          = (float*)d_out;           // (64, 2^20)

    dim3 grid(1024 / HI_PER_BLOCK, BATCH);         // (16, 64) = 1024 CTAs, one wave
    qansatz_kernel<<<grid, THREADS>>>(x, params, out);
}

// round 6
// speedup vs baseline: 1.1834x; 1.1834x over previous
#include <cuda_runtime.h>

// out[b, idx] = prod_w ( bit_{19-w}(idx) ? sin(h[b,w]) : cos(h[b,w]) ),
// h = (x + params) * 0.5. Wire w maps to idx bit (19-w).
// 8192 CTAs (128 x 64 batches): each CTA = one batch, 8 contiguous hi-values,
// one contiguous 32 KB store region. Fine granularity -> smooth wave refill,
// sustained store pressure, minimal tail raggedness.

#define N_WIRES 20
#define BATCH 64
#define HI_PER_BLOCK 8
#define THREADS 256

__global__ __launch_bounds__(THREADS, 8)
void qansatz_kernel(const float* __restrict__ x,
                    const float* __restrict__ params,
                    float* __restrict__ out)
{
    __shared__ float sc[N_WIRES];
    __shared__ float ss[N_WIRES];
    __shared__ float t_lo[1024];
    __shared__ float p_hi[HI_PER_BLOCK];

    const int b       = blockIdx.y;                    // batch
    const int hi_base = blockIdx.x * HI_PER_BLOCK;     // 128 blocks x 8 hi
    const int tid     = threadIdx.x;

    // 1) cos/sin for this batch's 20 wires
    if (tid < N_WIRES) {
        float h = (x[b * N_WIRES + tid] + params[tid]) * 0.5f;
        float c, s;
        sincosf(h, &s, &c);
        sc[tid] = c;
        ss[tid] = s;
    }
    __syncthreads();

    // 2) low-bits table: t_lo[lo] = prod_{q=0}^{9} (lo>>q & 1 ? ss[19-q] : sc[19-q])
    #pragma unroll
    for (int r = 0; r < 4; r++) {
        int lo = tid + r * 256;
        float p = 1.0f;
        #pragma unroll
        for (int q = 0; q < 10; q++)
            p *= ((lo >> q) & 1) ? ss[19 - q] : sc[19 - q];
        t_lo[lo] = p;
    }

    // 3) hi products: p_hi[i] = prod_{q=0}^{9} (h>>q & 1 ? ss[9-q] : sc[9-q])
    if (tid < HI_PER_BLOCK) {
        int h = hi_base + tid;
        float p = 1.0f;
        #pragma unroll
        for (int q = 0; q < 10; q++)
            p *= ((h >> q) & 1) ? ss[9 - q] : sc[9 - q];
        p_hi[tid] = p;
    }
    __syncthreads();

    // 4) stream out: 8 hi-values x 1024 floats, float4 per thread per iter.
    //    All 8 stores are independent -> full MLP, fire-and-forget.
    size_t base = ((size_t)b << 20) + ((size_t)hi_base << 10);
    const float4* t4 = reinterpret_cast<const float4*>(t_lo);
    float4 lo4 = t4[tid];
    float4* dst0 = reinterpret_cast<float4*>(out + base) + tid;

    #pragma unroll
    for (int i = 0; i < HI_PER_BLOCK; i++) {
        float ph = p_hi[i];
        float4 v;
        v.x = ph * lo4.x;
        v.y = ph * lo4.y;
        v.z = ph * lo4.z;
        v.w = ph * lo4.w;
        __stcs(dst0 + i * 256, v);   // streaming store: write-once output
    }
}

extern "C" void kernel_launch(void* const* d_in, const int* in_sizes, int n_in,
                              void* d_out, int out_size)
{
    const float* x      = (const float*)d_in[0];   // (64, 20)
    const float* params = (const float*)d_in[1];   // (20,)
    float* out          = (float*)d_out;           // (64, 2^20)

    dim3 grid(1024 / HI_PER_BLOCK, BATCH);         // (128, 64) = 8192 CTAs
    qansatz_kernel<<<grid, THREADS>>>(x, params, out);
}

// round 7
// speedup vs baseline: 1.2009x; 1.0149x over previous
#include <cuda_runtime.h>

// out[b, idx] = prod_w ( bit_{19-w}(idx) ? sin(h[b,w]) : cos(h[b,w]) ),
// h = (x + params) * 0.5. Wire w maps to idx bit (19-w).
//
// 16384 CTAs (256 x 64 batches). CTA = (batch b, 4 contiguous hi values),
// stores one contiguous 16 KB region. All products computed in registers via
// shared-prefix factoring (lo = 4*tid+j and hi = 4*bx+i each share bits 2..9),
// so setup is ~35 muls/thread, one barrier, no smem tables.

#define N_WIRES 20
#define BATCH 64
#define HI_PER_BLOCK 4
#define THREADS 256

__global__ __launch_bounds__(THREADS, 8)
void qansatz_kernel(const float* __restrict__ x,
                    const float* __restrict__ params,
                    float* __restrict__ out)
{
    __shared__ float sc[N_WIRES];
    __shared__ float ss[N_WIRES];

    const int b   = blockIdx.y;          // batch
    const int bx  = blockIdx.x;          // hi_base = 4*bx
    const int tid = threadIdx.x;

    // 1) cos/sin for this batch's 20 wires (one barrier)
    if (tid < N_WIRES) {
        float h = (x[b * N_WIRES + tid] + params[tid]) * 0.5f;
        float c, s;
        sincosf(h, &s, &c);
        sc[tid] = c;
        ss[tid] = s;
    }
    __syncthreads();

    // 2) lo part: this thread covers lo = 4*tid + j, j=0..3.
    //    lo bit q (q=2..9) = tid bit (q-2); factor = ss[19-q] : sc[19-q].
    float lo_common = 1.0f;
    #pragma unroll
    for (int q = 2; q < 10; q++)
        lo_common *= ((tid >> (q - 2)) & 1) ? ss[19 - q] : sc[19 - q];

    // j bit0 -> wire 19, j bit1 -> wire 18
    float lv0 = sc[19] * sc[18];   // j=0
    float lv1 = ss[19] * sc[18];   // j=1
    float lv2 = sc[19] * ss[18];   // j=2
    float lv3 = ss[19] * ss[18];   // j=3

    // 3) hi part: hi = 4*bx + i, i=0..3.
    //    hi bit q (q=2..9) = bx bit (q-2); factor = ss[9-q] : sc[9-q].
    float hi_common = 1.0f;
    #pragma unroll
    for (int q = 2; q < 10; q++)
        hi_common *= ((bx >> (q - 2)) & 1) ? ss[9 - q] : sc[9 - q];

    // i bit0 -> wire 9, i bit1 -> wire 8
    float hv0 = sc[9] * sc[8];     // i=0
    float hv1 = ss[9] * sc[8];     // i=1
    float hv2 = sc[9] * ss[8];     // i=2
    float hv3 = ss[9] * ss[8];     // i=3

    float base = lo_common * hi_common;
    float c0 = base * lv0, c1 = base * lv1, c2 = base * lv2, c3 = base * lv3;

    // 4) stream out: 4 hi-values x one float4/thread (independent stores)
    size_t off = ((size_t)b << 20) + ((size_t)bx << 12);
    float4* dst = reinterpret_cast<float4*>(out + off) + tid;

    float hv[4] = {hv0, hv1, hv2, hv3};
    #pragma unroll
    for (int i = 0; i < HI_PER_BLOCK; i++) {
        float ph = hv[i];
        float4 v;
        v.x = ph * c0;
        v.y = ph * c1;
        v.z = ph * c2;
        v.w = ph * c3;
        __stcs(dst + i * 256, v);    // streaming store: write-once output
    }
}

extern "C" void kernel_launch(void* const* d_in, const int* in_sizes, int n_in,
                              void* d_out, int out_size)
{
    const float* x      = (const float*)d_in[0];   // (64, 20)
    const float* params = (const float*)d_in[1];   // (20,)
    float* out          = (float*)d_out;           // (64, 2^20)

    dim3 grid(1024 / HI_PER_BLOCK, BATCH);         // (256, 64) = 16384 CTAs
    qansatz_kernel<<<grid, THREADS>>>(x, params, out);
}